// round 3
// baseline (speedup 1.0000x reference)
#include <cuda_runtime.h>
#include <cstdint>

// Problem constants (fixed by the dataset)
#define NN      100000      // nodes
#define NE      3200000     // edges
#define NFEAT   512
#define NHID    256
#define NCLASS  16
#define KHOPS   10

// ---------------------------------------------------------------------------
// Device scratch (no cudaMalloc allowed)
// ---------------------------------------------------------------------------
__device__ __align__(256) float g_deg[NN];              // degree, then dinv in-place
__device__ __align__(256) float g_norm[NE];             // per-edge norm
__device__ __align__(256) float g_h1[(size_t)NN * NHID];// relu(x@W1+b1), 102.4 MB
__device__ __align__(256) float g_hA[NN * NCLASS];      // ping
__device__ __align__(256) float g_hB[NN * NCLASS];      // pong

// ---------------------------------------------------------------------------
// Helpers
// ---------------------------------------------------------------------------
__device__ __forceinline__ void red_add_v4(float* p, float a, float b, float c, float d) {
    asm volatile("red.global.add.v4.f32 [%0], {%1,%2,%3,%4};"
                 :: "l"(p), "f"(a), "f"(b), "f"(c), "f"(d) : "memory");
}

// ---------------------------------------------------------------------------
// 0) zero scratch: g_deg (25000 float4) + g_hB (400000 float4)
// ---------------------------------------------------------------------------
__global__ void zero_scratch_kernel() {
    int i = blockIdx.x * blockDim.x + threadIdx.x;
    const float4 z = make_float4(0.f, 0.f, 0.f, 0.f);
    if (i < 25000) {
        reinterpret_cast<float4*>(g_deg)[i] = z;
    } else if (i < 25000 + 400000) {
        reinterpret_cast<float4*>(g_hB)[i - 25000] = z;
    }
}

// ---------------------------------------------------------------------------
// 1) degree over row
// ---------------------------------------------------------------------------
__global__ void degree_kernel(const int* __restrict__ row) {
    int e = blockIdx.x * blockDim.x + threadIdx.x;
    if (e < NE) atomicAdd(&g_deg[row[e]], 1.0f);
}

// 2) deg -> deg^{-1/2} in-place
__global__ void dinv_kernel() {
    int i = blockIdx.x * blockDim.x + threadIdx.x;
    if (i < NN) {
        float d = g_deg[i];
        g_deg[i] = (d > 0.f) ? rsqrtf(d) : 0.f;
    }
}

// 3) norm[e] = dinv[row]*dinv[col]
__global__ void norm_kernel(const int* __restrict__ row, const int* __restrict__ col) {
    int e = blockIdx.x * blockDim.x + threadIdx.x;
    if (e < NE) g_norm[e] = g_deg[row[e]] * g_deg[col[e]];
}

// ---------------------------------------------------------------------------
// 4) GEMM1: h1 = relu(x @ W1 + b1)   [NN,512]@[512,256]
//    64x256 block tile, BK=16, 256 threads, 8x8 microtile, reg prefetch.
// ---------------------------------------------------------------------------
#define G1_BM 64
#define G1_BK 16
#define G1_XSP 68   // padded stride for transposed x tile

__global__ void __launch_bounds__(256, 2) gemm1_kernel(
    const float* __restrict__ x, const float* __restrict__ W1,
    const float* __restrict__ b1)
{
    __shared__ float xs[G1_BK * G1_XSP];     // [k][m]
    __shared__ float w1s[G1_BK * NHID];      // [k][n]

    const int tid = threadIdx.x;
    const int rowBase = blockIdx.x * G1_BM;
    const int tr = tid >> 5;        // 0..7  -> rows tr*8..tr*8+7
    const int tc = tid & 31;        // 0..31 -> cols tc*8..tc*8+7

    // x-tile load mapping: one float4 per thread
    const int lm = tid >> 2;            // 0..63 row within tile
    const int lk = (tid & 3) * 4;       // k offset within tile
    const int xr = rowBase + lm;
    const bool xok = (xr < NN);

    // W1-tile load mapping: 4 float4 per thread
    int wk[4], wn[4];
#pragma unroll
    for (int i = 0; i < 4; i++) {
        int id = tid + i * 256;
        wk[i] = id >> 6;            // 0..15
        wn[i] = (id & 63) * 4;      // 0..252
    }

    float acc[8][8];
#pragma unroll
    for (int i = 0; i < 8; i++)
#pragma unroll
        for (int j = 0; j < 8; j++) acc[i][j] = 0.f;

    const float4 z4 = make_float4(0.f, 0.f, 0.f, 0.f);
    float4 fx;
    float4 fw[4];

    // prologue: load tile 0
    fx = xok ? *reinterpret_cast<const float4*>(&x[(size_t)xr * NFEAT + lk]) : z4;
#pragma unroll
    for (int i = 0; i < 4; i++)
        fw[i] = *reinterpret_cast<const float4*>(&W1[(size_t)wk[i] * NHID + wn[i]]);

    // store tile 0
    xs[(lk + 0) * G1_XSP + lm] = fx.x;
    xs[(lk + 1) * G1_XSP + lm] = fx.y;
    xs[(lk + 2) * G1_XSP + lm] = fx.z;
    xs[(lk + 3) * G1_XSP + lm] = fx.w;
#pragma unroll
    for (int i = 0; i < 4; i++)
        *reinterpret_cast<float4*>(&w1s[wk[i] * NHID + wn[i]]) = fw[i];
    __syncthreads();

    const int NSTEPS = NFEAT / G1_BK;   // 32
    for (int kb = 0; kb < NSTEPS; kb++) {
        // prefetch next tile into registers
        if (kb + 1 < NSTEPS) {
            int kBase = (kb + 1) * G1_BK;
            fx = xok ? *reinterpret_cast<const float4*>(&x[(size_t)xr * NFEAT + kBase + lk]) : z4;
#pragma unroll
            for (int i = 0; i < 4; i++)
                fw[i] = *reinterpret_cast<const float4*>(&W1[(size_t)(kBase + wk[i]) * NHID + wn[i]]);
        }
        // compute on current tile
#pragma unroll
        for (int k = 0; k < G1_BK; k++) {
            float a[8], b[8];
            float4 t;
            t = *reinterpret_cast<const float4*>(&xs[k * G1_XSP + tr * 8]);
            a[0] = t.x; a[1] = t.y; a[2] = t.z; a[3] = t.w;
            t = *reinterpret_cast<const float4*>(&xs[k * G1_XSP + tr * 8 + 4]);
            a[4] = t.x; a[5] = t.y; a[6] = t.z; a[7] = t.w;
            t = *reinterpret_cast<const float4*>(&w1s[k * NHID + tc * 8]);
            b[0] = t.x; b[1] = t.y; b[2] = t.z; b[3] = t.w;
            t = *reinterpret_cast<const float4*>(&w1s[k * NHID + tc * 8 + 4]);
            b[4] = t.x; b[5] = t.y; b[6] = t.z; b[7] = t.w;
#pragma unroll
            for (int i = 0; i < 8; i++)
#pragma unroll
                for (int j = 0; j < 8; j++)
                    acc[i][j] += a[i] * b[j];
        }
        if (kb + 1 < NSTEPS) {
            __syncthreads();
            xs[(lk + 0) * G1_XSP + lm] = fx.x;
            xs[(lk + 1) * G1_XSP + lm] = fx.y;
            xs[(lk + 2) * G1_XSP + lm] = fx.z;
            xs[(lk + 3) * G1_XSP + lm] = fx.w;
#pragma unroll
            for (int i = 0; i < 4; i++)
                *reinterpret_cast<float4*>(&w1s[wk[i] * NHID + wn[i]]) = fw[i];
            __syncthreads();
        }
    }

    // epilogue: bias + relu, store to g_h1
    float bv[8];
#pragma unroll
    for (int j = 0; j < 8; j++) bv[j] = b1[tc * 8 + j];

#pragma unroll
    for (int i = 0; i < 8; i++) {
        int r = rowBase + tr * 8 + i;
        if (r < NN) {
            float4 o0, o1;
            o0.x = fmaxf(acc[i][0] + bv[0], 0.f);
            o0.y = fmaxf(acc[i][1] + bv[1], 0.f);
            o0.z = fmaxf(acc[i][2] + bv[2], 0.f);
            o0.w = fmaxf(acc[i][3] + bv[3], 0.f);
            o1.x = fmaxf(acc[i][4] + bv[4], 0.f);
            o1.y = fmaxf(acc[i][5] + bv[5], 0.f);
            o1.z = fmaxf(acc[i][6] + bv[6], 0.f);
            o1.w = fmaxf(acc[i][7] + bv[7], 0.f);
            *reinterpret_cast<float4*>(&g_h1[(size_t)r * NHID + tc * 8])     = o0;
            *reinterpret_cast<float4*>(&g_h1[(size_t)r * NHID + tc * 8 + 4]) = o1;
        }
    }
}

// ---------------------------------------------------------------------------
// 5) GEMM2: h0 = h1 @ W2 + b2 -> g_hA; also out = gamma[0]*h0
//    thread-per-row, W2 staged in shared as float4 rows.
// ---------------------------------------------------------------------------
__global__ void gemm2_kernel(const float* __restrict__ W2, const float* __restrict__ b2,
                             const float* __restrict__ gamma, float* __restrict__ out)
{
    __shared__ float4 w2s[NHID * 4];    // W2[k][c] as 4 float4 per k
    const int tid = threadIdx.x;
#pragma unroll
    for (int i = 0; i < 4; i++) {
        int j = tid + i * 256;
        w2s[j] = reinterpret_cast<const float4*>(W2)[j];
    }
    __syncthreads();

    const int row = blockIdx.x * 256 + tid;
    if (row >= NN) return;

    float4 acc[4];
#pragma unroll
    for (int g = 0; g < 4; g++) acc[g] = reinterpret_cast<const float4*>(b2)[g];

    const float4* hr = reinterpret_cast<const float4*>(g_h1 + (size_t)row * NHID);
#pragma unroll 8
    for (int k4 = 0; k4 < NHID / 4; k4++) {
        float4 v = hr[k4];
        float s[4] = {v.x, v.y, v.z, v.w};
#pragma unroll
        for (int u = 0; u < 4; u++) {
#pragma unroll
            for (int g = 0; g < 4; g++) {
                float4 w = w2s[(k4 * 4 + u) * 4 + g];
                acc[g].x += s[u] * w.x;
                acc[g].y += s[u] * w.y;
                acc[g].z += s[u] * w.z;
                acc[g].w += s[u] * w.w;
            }
        }
    }

    float g0 = __ldg(&gamma[0]);
    float4* ha = reinterpret_cast<float4*>(g_hA) + row * 4;
    float4* op = reinterpret_cast<float4*>(out) + row * 4;
#pragma unroll
    for (int g = 0; g < 4; g++) {
        ha[g] = acc[g];
        float4 o;
        o.x = g0 * acc[g].x; o.y = g0 * acc[g].y;
        o.z = g0 * acc[g].z; o.w = g0 * acc[g].w;
        op[g] = o;
    }
}

// ---------------------------------------------------------------------------
// 6) scatter: hdst[col] += norm * hsrc[row]   (one thread per edge, RED.128 x4)
// ---------------------------------------------------------------------------
__global__ void scatter_kernel(const int* __restrict__ row, const int* __restrict__ col,
                               int flip)
{
    int e = blockIdx.x * blockDim.x + threadIdx.x;
    if (e >= NE) return;
    const float* src = flip ? g_hB : g_hA;
    float*       dst = flip ? g_hA : g_hB;

    int r = __ldg(&row[e]);
    int c = __ldg(&col[e]);
    float w = __ldg(&g_norm[e]);

    const float4* s = reinterpret_cast<const float4*>(src) + r * 4;
    float4 v0 = __ldg(s + 0), v1 = __ldg(s + 1), v2 = __ldg(s + 2), v3 = __ldg(s + 3);
    float* d = dst + c * NCLASS;
    red_add_v4(d + 0,  w * v0.x, w * v0.y, w * v0.z, w * v0.w);
    red_add_v4(d + 4,  w * v1.x, w * v1.y, w * v1.z, w * v1.w);
    red_add_v4(d + 8,  w * v2.x, w * v2.y, w * v2.z, w * v2.w);
    red_add_v4(d + 12, w * v3.x, w * v3.y, w * v3.z, w * v3.w);
}

// ---------------------------------------------------------------------------
// 7) finish: out += gamma[k]*h_new; zero old buffer for next iteration
// ---------------------------------------------------------------------------
__global__ void finish_kernel(float* __restrict__ out, const float* __restrict__ gamma,
                              int k, int flip)
{
    int i = blockIdx.x * blockDim.x + threadIdx.x;
    if (i >= NN * NCLASS / 4) return;
    const float4* hn = flip ? reinterpret_cast<const float4*>(g_hA)
                            : reinterpret_cast<const float4*>(g_hB);
    float4* hz = flip ? reinterpret_cast<float4*>(g_hB)
                      : reinterpret_cast<float4*>(g_hA);
    float g = __ldg(&gamma[k]);
    float4 v = hn[i];
    float4* op = reinterpret_cast<float4*>(out);
    float4 o = op[i];
    o.x += g * v.x; o.y += g * v.y; o.z += g * v.z; o.w += g * v.w;
    op[i] = o;
    hz[i] = make_float4(0.f, 0.f, 0.f, 0.f);
}

// ---------------------------------------------------------------------------
// Launch
// ---------------------------------------------------------------------------
extern "C" void kernel_launch(void* const* d_in, const int* in_sizes, int n_in,
                              void* d_out, int out_size)
{
    const float* x     = (const float*)d_in[0];
    const int*   ei    = (const int*)  d_in[1];
    const float* W1    = (const float*)d_in[2];
    const float* b1    = (const float*)d_in[3];
    const float* W2    = (const float*)d_in[4];
    const float* b2    = (const float*)d_in[5];
    const float* gamma = (const float*)d_in[6];
    float*       out   = (float*)d_out;

    const int* row = ei;         // edge_index[0]
    const int* col = ei + NE;    // edge_index[1]

    const int TPB = 256;
    const int ZB  = (25000 + 400000 + TPB - 1) / TPB;
    const int EB  = (NE + TPB - 1) / TPB;       // 12500
    const int NB  = (NN + TPB - 1) / TPB;       // 391
    const int FB  = (NN * NCLASS / 4 + TPB - 1) / TPB;  // 1563
    const int G1B = (NN + G1_BM - 1) / G1_BM;   // 1563

    zero_scratch_kernel<<<ZB, TPB>>>();
    degree_kernel<<<EB, TPB>>>(row);
    dinv_kernel<<<NB, TPB>>>();
    norm_kernel<<<EB, TPB>>>(row, col);
    gemm1_kernel<<<G1B, TPB>>>(x, W1, b1);
    gemm2_kernel<<<NB, TPB>>>(W2, b2, gamma, out);

    for (int k = 1; k <= KHOPS; k++) {
        int flip = (k - 1) & 1;
        scatter_kernel<<<EB, TPB>>>(row, col, flip);
        finish_kernel<<<FB, TPB>>>(out, gamma, k, flip);
    }
}

// round 4
// speedup vs baseline: 1.3822x; 1.3822x over previous
#include <cuda_runtime.h>
#include <cstdint>

// Problem constants (fixed by the dataset)
#define NN      100000      // nodes
#define NE      3200000     // edges
#define NFEAT   512
#define NHID    256
#define NCLASS  16
#define KHOPS   10

// ---------------------------------------------------------------------------
// Device scratch (no cudaMalloc allowed)
// ---------------------------------------------------------------------------
__device__ __align__(256) float g_deg[NN];               // degree -> dinv in-place
__device__ __align__(256) int   g_cnt[NN];               // in-degree (by col)
__device__ __align__(256) int   g_off[NN + 1];           // CSR offsets
__device__ __align__(256) int   g_cur[NN];               // fill cursors
__device__ __align__(256) int2  g_csr[NE];               // (src, bitcast norm)
__device__ __align__(256) float g_h1[(size_t)NN * NHID]; // relu(x@W1+b1)
__device__ __align__(256) float g_hA[NN * NCLASS];       // ping
__device__ __align__(256) float g_hB[NN * NCLASS];       // pong

// ---------------------------------------------------------------------------
// 0) zero: g_deg (float) + g_cnt (int), NN each
// ---------------------------------------------------------------------------
__global__ void zero_scratch_kernel() {
    int i = blockIdx.x * blockDim.x + threadIdx.x;
    if (i < NN / 4) {
        reinterpret_cast<float4*>(g_deg)[i] = make_float4(0.f, 0.f, 0.f, 0.f);
        reinterpret_cast<int4*>(g_cnt)[i]   = make_int4(0, 0, 0, 0);
    }
}

// ---------------------------------------------------------------------------
// 1) count: out-degree over row (float) + in-degree over col (int)
// ---------------------------------------------------------------------------
__global__ void count_kernel(const int* __restrict__ row, const int* __restrict__ col) {
    int e = blockIdx.x * blockDim.x + threadIdx.x;
    if (e < NE) {
        atomicAdd(&g_deg[row[e]], 1.0f);
        atomicAdd(&g_cnt[col[e]], 1);
    }
}

// 2) deg -> deg^{-1/2} in-place
__global__ void dinv_kernel() {
    int i = blockIdx.x * blockDim.x + threadIdx.x;
    if (i < NN) {
        float d = g_deg[i];
        g_deg[i] = (d > 0.f) ? rsqrtf(d) : 0.f;
    }
}

// ---------------------------------------------------------------------------
// 3) single-block exclusive scan of g_cnt -> g_off, init cursors
// ---------------------------------------------------------------------------
__global__ void scan_kernel() {
    __shared__ int sh[1024];
    const int tid = threadIdx.x;
    const int per = (NN + 1023) / 1024;   // 98
    int start = tid * per;
    int end = start + per; if (end > NN) end = NN;

    int s = 0;
    for (int i = start; i < end; i++) s += g_cnt[i];
    sh[tid] = s;
    __syncthreads();

    // Hillis-Steele inclusive scan over 1024 partial sums
    for (int off = 1; off < 1024; off <<= 1) {
        int v = (tid >= off) ? sh[tid - off] : 0;
        __syncthreads();
        sh[tid] += v;
        __syncthreads();
    }
    int run = (tid == 0) ? 0 : sh[tid - 1];

    for (int i = start; i < end; i++) {
        g_off[i] = run;
        g_cur[i] = run;
        run += g_cnt[i];
    }
    if (tid == 0) g_off[NN] = NE;
}

// ---------------------------------------------------------------------------
// 4) fill CSR: bucket edges by col, record (src, norm)
// ---------------------------------------------------------------------------
__global__ void fill_kernel(const int* __restrict__ row, const int* __restrict__ col) {
    int e = blockIdx.x * blockDim.x + threadIdx.x;
    if (e >= NE) return;
    int r = __ldg(&row[e]);
    int c = __ldg(&col[e]);
    float nrm = g_deg[r] * g_deg[c];            // g_deg holds dinv here
    int pos = atomicAdd(&g_cur[c], 1);
    g_csr[pos] = make_int2(r, __float_as_int(nrm));
}

// ---------------------------------------------------------------------------
// 5) GEMM1: h1 = relu(x @ W1 + b1)   [NN,512]@[512,256]
// ---------------------------------------------------------------------------
#define G1_BM 64
#define G1_BK 16
#define G1_XSP 68

__global__ void __launch_bounds__(256, 2) gemm1_kernel(
    const float* __restrict__ x, const float* __restrict__ W1,
    const float* __restrict__ b1)
{
    __shared__ float xs[G1_BK * G1_XSP];
    __shared__ float w1s[G1_BK * NHID];

    const int tid = threadIdx.x;
    const int rowBase = blockIdx.x * G1_BM;
    const int tr = tid >> 5;
    const int tc = tid & 31;

    const int lm = tid >> 2;
    const int lk = (tid & 3) * 4;
    const int xr = rowBase + lm;
    const bool xok = (xr < NN);

    int wk[4], wn[4];
#pragma unroll
    for (int i = 0; i < 4; i++) {
        int id = tid + i * 256;
        wk[i] = id >> 6;
        wn[i] = (id & 63) * 4;
    }

    float acc[8][8];
#pragma unroll
    for (int i = 0; i < 8; i++)
#pragma unroll
        for (int j = 0; j < 8; j++) acc[i][j] = 0.f;

    const float4 z4 = make_float4(0.f, 0.f, 0.f, 0.f);
    float4 fx;
    float4 fw[4];

    fx = xok ? *reinterpret_cast<const float4*>(&x[(size_t)xr * NFEAT + lk]) : z4;
#pragma unroll
    for (int i = 0; i < 4; i++)
        fw[i] = *reinterpret_cast<const float4*>(&W1[(size_t)wk[i] * NHID + wn[i]]);

    xs[(lk + 0) * G1_XSP + lm] = fx.x;
    xs[(lk + 1) * G1_XSP + lm] = fx.y;
    xs[(lk + 2) * G1_XSP + lm] = fx.z;
    xs[(lk + 3) * G1_XSP + lm] = fx.w;
#pragma unroll
    for (int i = 0; i < 4; i++)
        *reinterpret_cast<float4*>(&w1s[wk[i] * NHID + wn[i]]) = fw[i];
    __syncthreads();

    const int NSTEPS = NFEAT / G1_BK;
    for (int kb = 0; kb < NSTEPS; kb++) {
        if (kb + 1 < NSTEPS) {
            int kBase = (kb + 1) * G1_BK;
            fx = xok ? *reinterpret_cast<const float4*>(&x[(size_t)xr * NFEAT + kBase + lk]) : z4;
#pragma unroll
            for (int i = 0; i < 4; i++)
                fw[i] = *reinterpret_cast<const float4*>(&W1[(size_t)(kBase + wk[i]) * NHID + wn[i]]);
        }
#pragma unroll
        for (int k = 0; k < G1_BK; k++) {
            float a[8], b[8];
            float4 t;
            t = *reinterpret_cast<const float4*>(&xs[k * G1_XSP + tr * 8]);
            a[0] = t.x; a[1] = t.y; a[2] = t.z; a[3] = t.w;
            t = *reinterpret_cast<const float4*>(&xs[k * G1_XSP + tr * 8 + 4]);
            a[4] = t.x; a[5] = t.y; a[6] = t.z; a[7] = t.w;
            t = *reinterpret_cast<const float4*>(&w1s[k * NHID + tc * 8]);
            b[0] = t.x; b[1] = t.y; b[2] = t.z; b[3] = t.w;
            t = *reinterpret_cast<const float4*>(&w1s[k * NHID + tc * 8 + 4]);
            b[4] = t.x; b[5] = t.y; b[6] = t.z; b[7] = t.w;
#pragma unroll
            for (int i = 0; i < 8; i++)
#pragma unroll
                for (int j = 0; j < 8; j++)
                    acc[i][j] += a[i] * b[j];
        }
        if (kb + 1 < NSTEPS) {
            __syncthreads();
            xs[(lk + 0) * G1_XSP + lm] = fx.x;
            xs[(lk + 1) * G1_XSP + lm] = fx.y;
            xs[(lk + 2) * G1_XSP + lm] = fx.z;
            xs[(lk + 3) * G1_XSP + lm] = fx.w;
#pragma unroll
            for (int i = 0; i < 4; i++)
                *reinterpret_cast<float4*>(&w1s[wk[i] * NHID + wn[i]]) = fw[i];
            __syncthreads();
        }
    }

    float bv[8];
#pragma unroll
    for (int j = 0; j < 8; j++) bv[j] = b1[tc * 8 + j];

#pragma unroll
    for (int i = 0; i < 8; i++) {
        int r = rowBase + tr * 8 + i;
        if (r < NN) {
            float4 o0, o1;
            o0.x = fmaxf(acc[i][0] + bv[0], 0.f);
            o0.y = fmaxf(acc[i][1] + bv[1], 0.f);
            o0.z = fmaxf(acc[i][2] + bv[2], 0.f);
            o0.w = fmaxf(acc[i][3] + bv[3], 0.f);
            o1.x = fmaxf(acc[i][4] + bv[4], 0.f);
            o1.y = fmaxf(acc[i][5] + bv[5], 0.f);
            o1.z = fmaxf(acc[i][6] + bv[6], 0.f);
            o1.w = fmaxf(acc[i][7] + bv[7], 0.f);
            *reinterpret_cast<float4*>(&g_h1[(size_t)r * NHID + tc * 8])     = o0;
            *reinterpret_cast<float4*>(&g_h1[(size_t)r * NHID + tc * 8 + 4]) = o1;
        }
    }
}

// ---------------------------------------------------------------------------
// 6) GEMM2: h0 = h1 @ W2 + b2 -> g_hA; also out = gamma[0]*h0
// ---------------------------------------------------------------------------
__global__ void gemm2_kernel(const float* __restrict__ W2, const float* __restrict__ b2,
                             const float* __restrict__ gamma, float* __restrict__ out)
{
    __shared__ float4 w2s[NHID * 4];
    const int tid = threadIdx.x;
#pragma unroll
    for (int i = 0; i < 4; i++) {
        int j = tid + i * 256;
        w2s[j] = reinterpret_cast<const float4*>(W2)[j];
    }
    __syncthreads();

    const int row = blockIdx.x * 256 + tid;
    if (row >= NN) return;

    float4 acc[4];
#pragma unroll
    for (int g = 0; g < 4; g++) acc[g] = reinterpret_cast<const float4*>(b2)[g];

    const float4* hr = reinterpret_cast<const float4*>(g_h1 + (size_t)row * NHID);
#pragma unroll 8
    for (int k4 = 0; k4 < NHID / 4; k4++) {
        float4 v = hr[k4];
        float s[4] = {v.x, v.y, v.z, v.w};
#pragma unroll
        for (int u = 0; u < 4; u++) {
#pragma unroll
            for (int g = 0; g < 4; g++) {
                float4 w = w2s[(k4 * 4 + u) * 4 + g];
                acc[g].x += s[u] * w.x;
                acc[g].y += s[u] * w.y;
                acc[g].z += s[u] * w.z;
                acc[g].w += s[u] * w.w;
            }
        }
    }

    float g0 = __ldg(&gamma[0]);
    float4* ha = reinterpret_cast<float4*>(g_hA) + row * 4;
    float4* op = reinterpret_cast<float4*>(out) + row * 4;
#pragma unroll
    for (int g = 0; g < 4; g++) {
        ha[g] = acc[g];
        float4 o;
        o.x = g0 * acc[g].x; o.y = g0 * acc[g].y;
        o.z = g0 * acc[g].z; o.w = g0 * acc[g].w;
        op[g] = o;
    }
}

// ---------------------------------------------------------------------------
// 7) gather sweep: h_new[n] = sum_{e in CSR[n]} norm_e * h[src_e]
//    4 threads per node (one float4 chunk each); fused out += gamma[k]*h_new
// ---------------------------------------------------------------------------
__global__ void __launch_bounds__(256) gather_kernel(
    float* __restrict__ out, const float* __restrict__ gamma, int k, int flip)
{
    int t = blockIdx.x * blockDim.x + threadIdx.x;
    if (t >= NN * 4) return;
    int n = t >> 2;
    int c = t & 3;

    const float4* src = reinterpret_cast<const float4*>(flip ? g_hB : g_hA);
    float4*       dst = reinterpret_cast<float4*>(flip ? g_hA : g_hB);

    int e0 = __ldg(&g_off[n]);
    int e1 = __ldg(&g_off[n + 1]);

    float4 acc = make_float4(0.f, 0.f, 0.f, 0.f);
#pragma unroll 4
    for (int e = e0; e < e1; e++) {
        int2 er = __ldg(&g_csr[e]);
        float w = __int_as_float(er.y);
        float4 v = __ldg(&src[er.x * 4 + c]);
        acc.x += w * v.x;
        acc.y += w * v.y;
        acc.z += w * v.z;
        acc.w += w * v.w;
    }
    dst[n * 4 + c] = acc;

    float g = __ldg(&gamma[k]);
    float4* op = reinterpret_cast<float4*>(out) + n * 4 + c;
    float4 o = *op;
    o.x += g * acc.x; o.y += g * acc.y;
    o.z += g * acc.z; o.w += g * acc.w;
    *op = o;
}

// ---------------------------------------------------------------------------
// Launch
// ---------------------------------------------------------------------------
extern "C" void kernel_launch(void* const* d_in, const int* in_sizes, int n_in,
                              void* d_out, int out_size)
{
    const float* x     = (const float*)d_in[0];
    const int*   ei    = (const int*)  d_in[1];
    const float* W1    = (const float*)d_in[2];
    const float* b1    = (const float*)d_in[3];
    const float* W2    = (const float*)d_in[4];
    const float* b2    = (const float*)d_in[5];
    const float* gamma = (const float*)d_in[6];
    float*       out   = (float*)d_out;

    const int* row = ei;         // edge_index[0]
    const int* col = ei + NE;    // edge_index[1]

    const int TPB = 256;
    const int ZB  = (NN / 4 + TPB - 1) / TPB;
    const int EB  = (NE + TPB - 1) / TPB;        // 12500
    const int NB  = (NN + TPB - 1) / TPB;        // 391
    const int GB  = (NN * 4 + TPB - 1) / TPB;    // 1563
    const int G1B = (NN + G1_BM - 1) / G1_BM;    // 1563

    zero_scratch_kernel<<<ZB, TPB>>>();
    count_kernel<<<EB, TPB>>>(row, col);
    dinv_kernel<<<NB, TPB>>>();
    scan_kernel<<<1, 1024>>>();
    fill_kernel<<<EB, TPB>>>(row, col);
    gemm1_kernel<<<G1B, TPB>>>(x, W1, b1);
    gemm2_kernel<<<NB, TPB>>>(W2, b2, gamma, out);

    for (int k = 1; k <= KHOPS; k++) {
        int flip = (k - 1) & 1;
        gather_kernel<<<GB, TPB>>>(out, gamma, k, flip);
    }
}